// round 1
// baseline (speedup 1.0000x reference)
#include <cuda_runtime.h>
#include <math.h>

#define F_EPS 1e-9f
#define F_COS_EPS 1e-8f

constexpr int S = 48;
constexpr int MD = 10;
constexpr int H = 48;
constexpr int NFEAT = 60;
constexpr int RS = 11;        // padded row stride for shared coords (coprime with 32)
constexpr int WPB = 8;        // warps (trajectories) per block
constexpr int TPB = WPB * 32;

__device__ __forceinline__ float wsum(float v) {
#pragma unroll
    for (int o = 16; o; o >>= 1) v += __shfl_xor_sync(0xffffffffu, v, o);
    return v;
}
__device__ __forceinline__ float wmaxr(float v) {
#pragma unroll
    for (int o = 16; o; o >>= 1) v = fmaxf(v, __shfl_xor_sync(0xffffffffu, v, o));
    return v;
}
__device__ __forceinline__ float wminr(float v) {
#pragma unroll
    for (int o = 16; o; o >>= 1) v = fminf(v, __shfl_xor_sync(0xffffffffu, v, o));
    return v;
}

__global__ void __launch_bounds__(TPB)
traj_feat_kernel(const float* __restrict__ coords,
                 const int*   __restrict__ lengths,
                 const float* __restrict__ Wg,
                 const float* __restrict__ bg,
                 const float* __restrict__ lnwg,
                 const float* __restrict__ lnbg,
                 float* __restrict__ out,
                 int B)
{
    __shared__ float sW[NFEAT * H];
    __shared__ float sb[H], slw[H], slb[H];
    __shared__ float sc[WPB][S * RS];
    __shared__ float sfeat[WPB][64];

    const int tid = threadIdx.x;
    for (int i = tid; i < NFEAT * H; i += TPB) sW[i] = Wg[i];
    if (tid < H) { sb[tid] = bg[tid]; slw[tid] = lnwg[tid]; slb[tid] = lnbg[tid]; }
    __syncthreads();

    const int w    = tid >> 5;
    const int lane = tid & 31;
    const int traj = blockIdx.x * WPB + w;
    if (traj >= B) return;

    const int   n    = lengths[traj];
    const float nf   = (float)n;
    const int   m    = n - 1;
    const float mf   = (float)m;
    const int   half = m >> 1;

    // ---- stage coords to shared (coalesced), fused coord mean/var accumulation ----
    const float* cp = coords + (size_t)traj * (S * MD);
    float* c = sc[w];
    float csum = 0.f, cssum = 0.f;
#pragma unroll
    for (int e = lane; e < S * MD; e += 32) {
        float v = cp[e];
        int r = e / MD;
        int col = e - r * MD;
        c[r * RS + col] = v;
        if (r < n) { csum += v; cssum += v * v; }
    }
    __syncwarp();

    // ---- per-delta statistics ----
    float path = 0.f, fsum = 0.f, shsum = 0.f, maxdm = -INFINITY, dmsq = 0.f;
    float us[MD];
#pragma unroll
    for (int k = 0; k < MD; k++) us[k] = 0.f;
    float uss = 0.f;
    float cvsum = 0.f, cvsq = 0.f, maxcv = -INFINITY, mincv = INFINITY;
    float cossum = 0.f, mincos = INFINITY, dirch = 0.f;

#pragma unroll
    for (int rep = 0; rep < 2; rep++) {
        int i = lane + rep * 32;
        if (i < S - 1) {
            bool valid = i < m;
            float d[MD];
            float ss = 0.f;
#pragma unroll
            for (int k = 0; k < MD; k++) {
                float dd = c[(i + 1) * RS + k] - c[i * RS + k];
                dd = valid ? dd : 0.f;
                d[k] = dd;
                ss += dd * dd;
            }
            float dmag = (ss > 0.f) ? sqrtf(fmaxf(ss, 1e-30f)) : 0.f;
            float na   = fmaxf(dmag, F_COS_EPS);

            path += dmag;
            if (i < half + 1) fsum += dmag;
            if (i >= half && i < m) shsum += dmag;
            if (valid) maxdm = fmaxf(maxdm, dmag);
            dmsq += dmag * dmag;

            float rin = 1.0f / na;
#pragma unroll
            for (int k = 0; k < MD; k++) {
                float u = d[k] * rin;
                us[k] += u;
                uss += u * u;
            }

            if (rep == 0 && lane < 3) {
#pragma unroll
                for (int k = 0; k < MD; k++) sfeat[w][21 + lane * MD + k] = d[k];
            }

            if (i < S - 2) {
                float curvout = 0.f;
                if (i < n - 2) {   // implies i+1 < m: next delta valid unmasked
                    float ssn = 0.f, dp = 0.f;
#pragma unroll
                    for (int k = 0; k < MD; k++) {
                        float dn = c[(i + 2) * RS + k] - c[(i + 1) * RS + k];
                        ssn += dn * dn;
                        dp  += d[k] * dn;
                    }
                    float dmn  = (ssn > 0.f) ? sqrtf(fmaxf(ssn, 1e-30f)) : 0.f;
                    float nan_ = fmaxf(dmn, F_COS_EPS);
                    float cosv = dp / (na * nan_);
                    float curv = 1.0f - cosv;
                    cvsum += curv;
                    cvsq  += curv * curv;
                    maxcv = fmaxf(maxcv, curv);
                    mincv = fminf(mincv, curv);
                    cossum += cosv;
                    mincos = fminf(mincos, cosv);
                    dirch += (cosv < 0.f) ? 1.f : 0.f;
                    curvout = curv;
                }
                if (rep == 0 && lane < 9) sfeat[w][51 + lane] = curvout;
            }
        }
    }

    // total displacement
    float tdp = 0.f;
    if (lane < MD) {
        float dd = c[(n - 1) * RS + lane] - c[lane];
        tdp = dd * dd;
    }

    // ---- warp reductions ----
    path  = wsum(path);  fsum  = wsum(fsum);  shsum = wsum(shsum);
    dmsq  = wsum(dmsq);  maxdm = wmaxr(maxdm);
    uss   = wsum(uss);
#pragma unroll
    for (int k = 0; k < MD; k++) us[k] = wsum(us[k]);
    cvsum = wsum(cvsum); cvsq = wsum(cvsq);
    maxcv = wmaxr(maxcv); mincv = wminr(mincv);
    cossum = wsum(cossum); mincos = wminr(mincos); dirch = wsum(dirch);
    csum = wsum(csum); cssum = wsum(cssum);
    tdp  = wsum(tdp);

    if (lane == 0) {
        float total_disp = (tdp > 0.f) ? sqrtf(fmaxf(tdp, 1e-30f)) : 0.f;
        float disp_ratio = total_disp / (path + F_EPS);
        float ncf = (float)(n - 2);
        float mean_curv = cvsum / ncf;
        float curv_var  = (cvsq - ncf * mean_curv * mean_curv) / fmaxf(ncf - 1.f, 1.f);
        float std_curv  = (ncf > 1.f) ? sqrtf(fmaxf(curv_var, 1e-30f)) : 0.f;
        float mean_cos  = cossum / ncf;
        float dir_chg   = dirch / fmaxf(ncf, 1.f);
        float loop_score = 1.f - total_disp / (path + F_EPS);
        float fh = fsum / (float)(half + 1);
        float sh = shsum / (float)(m - half);
        float conv = (fh - sh) / (fh + F_EPS);
        float casc = (sh - fh) / (fh + F_EPS);
        float nsq = 0.f;
#pragma unroll
        for (int k = 0; k < MD; k++) nsq += us[k] * us[k];
        float npairs = mf * (mf - 1.f) * 0.5f;
        float par = 0.5f * (nsq - uss) / fmaxf(npairs, 1.f);
        float mean_dm = path / mf;
        float dm_var  = (dmsq - mf * mean_dm * mean_dm) / fmaxf(mf - 1.f, 1.f);
        float std_dm  = (mf > 1.f) ? sqrtf(fmaxf(dm_var, 1e-30f)) : 0.f;
        float jump = (mean_dm > F_EPS) ? maxdm / mean_dm : 1.f;
        float cnt  = nf * (float)MD;
        float mc   = csum / cnt;
        float cvar = (cssum - cnt * mc * mc) / (cnt - 1.f);
        float stdc = sqrtf(fmaxf(cvar, 1e-30f));

        float* sf = sfeat[w];
        sf[0]  = total_disp;
        sf[1]  = path;
        sf[2]  = disp_ratio;
        sf[3]  = nf * 0.1f;
        sf[4]  = mean_curv;
        sf[5]  = maxcv;
        sf[6]  = std_curv;
        sf[7]  = maxcv - mincv;
        sf[8]  = mean_cos;
        sf[9]  = mincos;
        sf[10] = dir_chg;
        sf[11] = disp_ratio;
        sf[12] = loop_score;
        sf[13] = conv;
        sf[14] = par;
        sf[15] = jump;
        sf[16] = casc;
        sf[17] = mean_dm;
        sf[18] = std_dm;
        sf[19] = mc;
        sf[20] = stdc;
    }
    __syncwarp();

    // ---- h = feats @ W + b ; LayerNorm ; exact GELU ----
    const float* sf = sfeat[w];
    float h0 = sb[lane];
    float h1 = (lane < 16) ? sb[32 + lane] : 0.f;
    const int j2 = 32 + (lane & 15);
#pragma unroll
    for (int f = 0; f < NFEAT; f++) {
        float fv = sf[f];
        h0 = fmaf(fv, sW[f * H + lane], h0);
        float wv2 = sW[f * H + j2];
        if (lane < 16) h1 = fmaf(fv, wv2, h1);
    }

    float partial = h0 + ((lane < 16) ? h1 : 0.f);
    float mu = wsum(partial) / 48.0f;
    float e0 = h0 - mu;
    float e1 = h1 - mu;
    float vpart = e0 * e0 + ((lane < 16) ? e1 * e1 : 0.f);
    float var = wsum(vpart) / 48.0f;
    float inv = 1.0f / sqrtf(var + 1e-5f);

    float y0 = e0 * inv * slw[lane] + slb[lane];
    float g0 = 0.5f * y0 * (1.0f + erff(y0 * 0.70710678118654752f));
    out[(size_t)traj * H + lane] = g0;
    if (lane < 16) {
        float y1 = e1 * inv * slw[32 + lane] + slb[32 + lane];
        float g1 = 0.5f * y1 * (1.0f + erff(y1 * 0.70710678118654752f));
        out[(size_t)traj * H + 32 + lane] = g1;
    }
}

extern "C" void kernel_launch(void* const* d_in, const int* in_sizes, int n_in,
                              void* d_out, int out_size) {
    const float* coords  = (const float*)d_in[0];
    const int*   lengths = (const int*)d_in[1];
    const float* W       = (const float*)d_in[2];
    const float* b       = (const float*)d_in[3];
    const float* lnw     = (const float*)d_in[4];
    const float* lnb     = (const float*)d_in[5];
    float* out = (float*)d_out;

    int B = in_sizes[1];                 // lengths element count
    int grid = (B + WPB - 1) / WPB;
    traj_feat_kernel<<<grid, TPB>>>(coords, lengths, W, b, lnw, lnb, out, B);
}

// round 2
// speedup vs baseline: 1.2989x; 1.2989x over previous
#include <cuda_runtime.h>
#include <math.h>

#define F_EPS 1e-9f
#define F_INF __int_as_float(0x7f800000)

constexpr int MD   = 10;
constexpr int WPB  = 4;            // warps (trajectories) per block in K1
constexpr int TPB1 = WPB * 32;
constexpr int TB   = 128;          // trajectories per block in K2
constexpr int H    = 48;
constexpr int NF   = 60;

// scratch: feats padded to stride 64 (max 65536 trajectories)
__device__ float g_feats[65536 * 64];

__device__ __forceinline__ float wsum(float v) {
#pragma unroll
    for (int o = 16; o; o >>= 1) v += __shfl_xor_sync(0xffffffffu, v, o);
    return v;
}
__device__ __forceinline__ float wmaxr(float v) {
#pragma unroll
    for (int o = 16; o; o >>= 1) v = fmaxf(v, __shfl_xor_sync(0xffffffffu, v, o));
    return v;
}
__device__ __forceinline__ float wminr(float v) {
#pragma unroll
    for (int o = 16; o; o >>= 1) v = fminf(v, __shfl_xor_sync(0xffffffffu, v, o));
    return v;
}

// ------------------------------- K1: features -------------------------------
__global__ void __launch_bounds__(TPB1)
k1_features(const float* __restrict__ coords, const int* __restrict__ lengths, int B)
{
    __shared__ float sfeat[WPB][NF];

    const unsigned FULL = 0xffffffffu;
    const int w    = threadIdx.x >> 5;
    const int lane = threadIdx.x & 31;
    const int traj = blockIdx.x * WPB + w;
    if (traj >= B) return;

    const int   n    = lengths[traj];
    const int   m    = n - 1;
    const int   half = m >> 1;          // half <= 23 always (m <= 47)
    const float nf   = (float)n;
    const float mf   = (float)m;

    // ---- rows in registers: lane holds row `lane` and row `lane+32` ----
    const float* cp = coords + (size_t)traj * 480;
    float r0[MD], r1[MD];
    {
        const float2* p0 = (const float2*)(cp + lane * MD);
#pragma unroll
        for (int k = 0; k < 5; k++) { float2 v = p0[k]; r0[2*k] = v.x; r0[2*k+1] = v.y; }
    }
    if (lane < 16) {
        const float2* p1 = (const float2*)(cp + (lane + 32) * MD);
#pragma unroll
        for (int k = 0; k < 5; k++) { float2 v = p1[k]; r1[2*k] = v.x; r1[2*k+1] = v.y; }
    } else {
#pragma unroll
        for (int k = 0; k < MD; k++) r1[k] = 0.f;
    }

    // ---- coord mean/var partials ----
    float csum = 0.f, cssum = 0.f;
    if (lane < n) {
#pragma unroll
        for (int k = 0; k < MD; k++) { csum += r0[k]; cssum += r0[k] * r0[k]; }
    }
    if (lane + 32 < n) {
#pragma unroll
        for (int k = 0; k < MD; k++) { csum += r1[k]; cssum += r1[k] * r1[k]; }
    }

    // ---- total displacement (computed redundantly by every lane) ----
    const bool hiLast = (n > 32);       // uniform within warp
    float tdp = 0.f;
#pragma unroll
    for (int k = 0; k < MD; k++) {
        float fst = __shfl_sync(FULL, r0[k], 0);
        float lst = __shfl_sync(FULL, hiLast ? r1[k] : r0[k], hiLast ? (n - 33) : (n - 1));
        float dd = lst - fst;
        tdp += dd * dd;
    }

    // ---- deltas via shuffles ----
    const bool v0 = lane < m;           // delta index i0 = lane
    const bool v1 = lane + 32 < m;      // delta index i1 = lane + 32
    float d0[MD], d1[MD];
    float ss0 = 0.f, ss1 = 0.f;
#pragma unroll
    for (int k = 0; k < MD; k++) {
        float nx0 = __shfl_down_sync(FULL, r0[k], 1);
        float b32 = __shfl_sync(FULL, r1[k], 0);       // row 32
        if (lane == 31) nx0 = b32;
        float nx1 = __shfl_down_sync(FULL, r1[k], 1);
        float a = v0 ? (nx0 - r0[k]) : 0.f;
        float b = v1 ? (nx1 - r1[k]) : 0.f;
        d0[k] = a; d1[k] = b;
        ss0 += a * a; ss1 += b * b;
    }
    float dmag0 = (ss0 > 0.f) ? sqrtf(fmaxf(ss0, 1e-30f)) : 0.f;
    float dmag1 = (ss1 > 0.f) ? sqrtf(fmaxf(ss1, 1e-30f)) : 0.f;
    float na0 = fmaxf(dmag0, 1e-8f), na1 = fmaxf(dmag1, 1e-8f);
    float rin0 = 1.0f / na0, rin1 = 1.0f / na1;

    // ---- dmag stats (half <= 23 so first-half is rep0-only) ----
    float fsum  = (lane < half + 1) ? dmag0 : 0.f;
    float shsum = ((lane >= half) && v0 ? dmag0 : 0.f) + (v1 ? dmag1 : 0.f);
    float dmsq  = dmag0 * dmag0 + dmag1 * dmag1;
    float maxdm = fmaxf(v0 ? dmag0 : -F_INF, v1 ? dmag1 : -F_INF);
    float dhalf = __shfl_sync(FULL, dmag0, half);      // path = fsum+shsum-dhalf

    // ---- unit vectors + curvature dots via shuffled deltas ----
    float us[MD], uss = 0.f, dot0 = 0.f, dot1 = 0.f;
#pragma unroll
    for (int k = 0; k < MD; k++) {
        float u0 = d0[k] * rin0, u1 = d1[k] * rin1;
        us[k] = u0 + u1;
        uss += u0 * u0 + u1 * u1;
        float dn0 = __shfl_down_sync(FULL, d0[k], 1);
        float c32 = __shfl_sync(FULL, d1[k], 0);       // delta 32
        if (lane == 31) dn0 = c32;
        float dn1 = __shfl_down_sync(FULL, d1[k], 1);
        dot0 += d0[k] * dn0;
        dot1 += d1[k] * dn1;
    }
    float nan0 = __shfl_down_sync(FULL, na0, 1);
    {
        float t = __shfl_sync(FULL, na1, 0);
        if (lane == 31) nan0 = t;
    }
    float nan1 = __shfl_down_sync(FULL, na1, 1);
    float cos0 = dot0 / (na0 * nan0);
    float cos1 = dot1 / (na1 * nan1);
    const bool c0 = lane < n - 2;
    const bool c1 = lane + 32 < n - 2;

    float cossum = (c0 ? cos0 : 0.f) + (c1 ? cos1 : 0.f);
    float cossq  = (c0 ? cos0 * cos0 : 0.f) + (c1 ? cos1 * cos1 : 0.f);
    float mincs  = fminf(c0 ? cos0 : F_INF, c1 ? cos1 : F_INF);
    float maxcs  = fmaxf(c0 ? cos0 : -F_INF, c1 ? cos1 : -F_INF);
    float dirch  = ((c0 && cos0 < 0.f) ? 1.f : 0.f) + ((c1 && cos1 < 0.f) ? 1.f : 0.f);

    // ---- padded deltas / curvs ----
    if (lane < 3) {
#pragma unroll
        for (int k = 0; k < MD; k++) sfeat[w][21 + lane * MD + k] = d0[k];
    }
    if (lane < 9) sfeat[w][51 + lane] = c0 ? (1.0f - cos0) : 0.f;

    // ---- warp reductions ----
    fsum  = wsum(fsum);  shsum = wsum(shsum); dmsq = wsum(dmsq);
    maxdm = wmaxr(maxdm); uss = wsum(uss);
#pragma unroll
    for (int k = 0; k < MD; k++) us[k] = wsum(us[k]);
    cossum = wsum(cossum); cossq = wsum(cossq);
    mincs = wminr(mincs);  maxcs = wmaxr(maxcs);
    dirch = wsum(dirch);
    csum = wsum(csum); cssum = wsum(cssum);

    if (lane == 0) {
        float path = fsum + shsum - dhalf;
        float total_disp = (tdp > 0.f) ? sqrtf(fmaxf(tdp, 1e-30f)) : 0.f;
        float disp_ratio = total_disp / (path + F_EPS);
        float ncf = (float)(n - 2);
        float mean_cos  = cossum / ncf;
        float mean_curv = (ncf - cossum) / ncf;
        float max_curv  = 1.0f - mincs;
        float cvsq      = ncf - 2.0f * cossum + cossq;
        float curv_var  = (cvsq - ncf * mean_curv * mean_curv) / fmaxf(ncf - 1.f, 1.f);
        float std_curv  = (ncf > 1.f) ? sqrtf(fmaxf(curv_var, 1e-30f)) : 0.f;
        float curv_range = maxcs - mincs;   // (1-mincs)-(1-maxcs)
        float dir_chg   = dirch / fmaxf(ncf, 1.f);
        float loop_score = 1.f - total_disp / (path + F_EPS);
        float fh = fsum / (float)(half + 1);
        float sh = shsum / (float)(m - half);
        float conv = (fh - sh) / (fh + F_EPS);
        float casc = (sh - fh) / (fh + F_EPS);
        float nsq = 0.f;
#pragma unroll
        for (int k = 0; k < MD; k++) nsq += us[k] * us[k];
        float npairs = mf * (mf - 1.f) * 0.5f;
        float par = 0.5f * (nsq - uss) / fmaxf(npairs, 1.f);
        float mean_dm = path / mf;
        float dm_var  = (dmsq - mf * mean_dm * mean_dm) / fmaxf(mf - 1.f, 1.f);
        float std_dm  = (mf > 1.f) ? sqrtf(fmaxf(dm_var, 1e-30f)) : 0.f;
        float jump = (mean_dm > F_EPS) ? maxdm / mean_dm : 1.f;
        float cnt  = nf * (float)MD;
        float mc   = csum / cnt;
        float cvar = (cssum - cnt * mc * mc) / (cnt - 1.f);
        float stdc = sqrtf(fmaxf(cvar, 1e-30f));

        float* sf = sfeat[w];
        sf[0]  = total_disp;  sf[1]  = path;        sf[2]  = disp_ratio;
        sf[3]  = nf * 0.1f;   sf[4]  = mean_curv;   sf[5]  = max_curv;
        sf[6]  = std_curv;    sf[7]  = curv_range;  sf[8]  = mean_cos;
        sf[9]  = mincs;       sf[10] = dir_chg;     sf[11] = disp_ratio;
        sf[12] = loop_score;  sf[13] = conv;        sf[14] = par;
        sf[15] = jump;        sf[16] = casc;        sf[17] = mean_dm;
        sf[18] = std_dm;      sf[19] = mc;          sf[20] = stdc;
    }
    __syncwarp();

    float* gout = g_feats + (size_t)traj * 64;
    if (lane < 30) {
        gout[lane]      = sfeat[w][lane];
        gout[30 + lane] = sfeat[w][30 + lane];
    }
}

// --------------------- K2: GEMM + LayerNorm + GELU --------------------------
__device__ __forceinline__ unsigned long long pk2(float a, float b) {
    unsigned long long r;
    asm("mov.b64 %0, {%1, %2};" : "=l"(r) : "f"(a), "f"(b));
    return r;
}
__device__ __forceinline__ void upk2(unsigned long long v, float& a, float& b) {
    asm("mov.b64 {%0, %1}, %2;" : "=f"(a), "=f"(b) : "l"(v));
}
__device__ __forceinline__ unsigned long long fma2(unsigned long long a,
                                                   unsigned long long b,
                                                   unsigned long long c) {
    unsigned long long d;
    asm("fma.rn.f32x2 %0, %1, %2, %3;" : "=l"(d) : "l"(a), "l"(b), "l"(c));
    return d;
}

__global__ void __launch_bounds__(128)
k2_head(const float* __restrict__ Wg, const float* __restrict__ bg,
        const float* __restrict__ lnwg, const float* __restrict__ lnbg,
        float* __restrict__ out, int B)
{
    __shared__ float sW[NF * H];          // 11.25 KB
    __shared__ float sfe[TB * 61];        // 30.5 KB (pad 61 vs bank conflicts)

    const unsigned FULL = 0xffffffffu;
    const int tid = threadIdx.x;
    const int t0  = blockIdx.x * TB;

    for (int i = tid; i < NF * H; i += 128) sW[i] = Wg[i];
    for (int i = tid; i < TB * NF; i += 128) {
        int r = i / NF, f = i - r * NF;
        sfe[r * 61 + f] = g_feats[(size_t)(t0 + r) * 64 + f];
    }
    __syncthreads();

    const int tx = tid & 7;               // 8 column groups of 6
    const int ty = tid >> 3;              // 16 row groups of 8
    const int colb = tx * 6;

    // init accumulators with bias
    unsigned long long acc[8][3];
    {
        unsigned long long b0 = pk2(bg[colb + 0], bg[colb + 1]);
        unsigned long long b1 = pk2(bg[colb + 2], bg[colb + 3]);
        unsigned long long b2 = pk2(bg[colb + 4], bg[colb + 5]);
#pragma unroll
        for (int r = 0; r < 8; r++) { acc[r][0] = b0; acc[r][1] = b1; acc[r][2] = b2; }
    }

    const float* fbase = sfe + ty * 8 * 61;
#pragma unroll 4
    for (int f = 0; f < NF; f++) {
        unsigned long long w0 = *(const unsigned long long*)(sW + f * H + colb);
        unsigned long long w1 = *(const unsigned long long*)(sW + f * H + colb + 2);
        unsigned long long w2 = *(const unsigned long long*)(sW + f * H + colb + 4);
#pragma unroll
        for (int r = 0; r < 8; r++) {
            float fv = fbase[r * 61 + f];
            unsigned long long fp = pk2(fv, fv);
            acc[r][0] = fma2(fp, w0, acc[r][0]);
            acc[r][1] = fma2(fp, w1, acc[r][1]);
            acc[r][2] = fma2(fp, w2, acc[r][2]);
        }
    }

    // per-thread LN params for its 6 columns
    float lw[6], lb[6];
#pragma unroll
    for (int c = 0; c < 6; c++) { lw[c] = lnwg[colb + c]; lb[c] = lnbg[colb + c]; }

    // LN over 48 cols: 8 lanes (same ty-quad) hold a row's 48 values
#pragma unroll
    for (int r = 0; r < 8; r++) {
        float x[6];
        upk2(acc[r][0], x[0], x[1]);
        upk2(acc[r][1], x[2], x[3]);
        upk2(acc[r][2], x[4], x[5]);
        float s = 0.f, sq = 0.f;
#pragma unroll
        for (int c = 0; c < 6; c++) { s += x[c]; sq += x[c] * x[c]; }
#pragma unroll
        for (int o = 1; o < 8; o <<= 1) {
            s  += __shfl_xor_sync(FULL, s,  o);
            sq += __shfl_xor_sync(FULL, sq, o);
        }
        float mu  = s * (1.0f / 48.0f);
        float var = sq * (1.0f / 48.0f) - mu * mu;
        float inv = rsqrtf(var + 1e-5f);

        int row = t0 + ty * 8 + r;
        if (row < B) {
            float y[6];
#pragma unroll
            for (int c = 0; c < 6; c++) {
                float v = (x[c] - mu) * inv * lw[c] + lb[c];
                y[c] = 0.5f * v * (1.0f + erff(v * 0.70710678118654752f));
            }
            float* op = out + (size_t)row * H + colb;
            *(float2*)(op + 0) = make_float2(y[0], y[1]);
            *(float2*)(op + 2) = make_float2(y[2], y[3]);
            *(float2*)(op + 4) = make_float2(y[4], y[5]);
        }
    }
}

extern "C" void kernel_launch(void* const* d_in, const int* in_sizes, int n_in,
                              void* d_out, int out_size) {
    const float* coords  = (const float*)d_in[0];
    const int*   lengths = (const int*)d_in[1];
    const float* W       = (const float*)d_in[2];
    const float* b       = (const float*)d_in[3];
    const float* lnw     = (const float*)d_in[4];
    const float* lnb     = (const float*)d_in[5];
    float* out = (float*)d_out;

    int B = in_sizes[1];
    int g1 = (B + WPB - 1) / WPB;
    k1_features<<<g1, TPB1>>>(coords, lengths, B);
    int g2 = (B + TB - 1) / TB;
    k2_head<<<g2, 128>>>(W, b, lnw, lnb, out, B);
}

// round 3
// speedup vs baseline: 1.4465x; 1.1136x over previous
#include <cuda_runtime.h>
#include <math.h>

#define F_EPS 1e-9f
#define F_INF __int_as_float(0x7f800000)

constexpr int MD   = 10;
constexpr int WPB  = 4;            // warps (trajectories) per block in K1
constexpr int TPB1 = WPB * 32;
constexpr int TB   = 64;           // trajectories per block in K2
constexpr int H    = 48;
constexpr int NF   = 60;

// scratch: feats padded to stride 64 (max 65536 trajectories)
__device__ float g_feats[65536 * 64];

#define FULLM 0xffffffffu

// merge-reduce: one shuffle advances TWO accumulators one level.
// Result: x's reduction lives on lanes with `bit` clear, y's on lanes with `bit` set.
__device__ __forceinline__ float mrg(float x, float y, int bit, int lane) {
    float sel = (lane & bit) ? x : y;
    float rec = __shfl_xor_sync(FULLM, sel, bit);
    return (lane & bit) ? (y + rec) : (x + rec);
}
__device__ __forceinline__ float mrgmax(float x, float y, int bit, int lane) {
    float sel = (lane & bit) ? x : y;
    float rec = __shfl_xor_sync(FULLM, sel, bit);
    return (lane & bit) ? fmaxf(y, rec) : fmaxf(x, rec);
}
__device__ __forceinline__ float solo(float x, int bit) {
    return x + __shfl_xor_sync(FULLM, x, bit);
}
__device__ __forceinline__ float solomax(float x, int bit) {
    return fmaxf(x, __shfl_xor_sync(FULLM, x, bit));
}

// ------------------------------- K1: features -------------------------------
__global__ void __launch_bounds__(TPB1)
k1_features(const float* __restrict__ coords, const int* __restrict__ lengths, int B)
{
    __shared__ float sfeat[WPB][NF];
    __shared__ float sred[WPB][64];

    const int w    = threadIdx.x >> 5;
    const int lane = threadIdx.x & 31;
    const int traj = blockIdx.x * WPB + w;
    if (traj >= B) return;

    const int   n    = lengths[traj];
    const int   m    = n - 1;
    const int   half = m >> 1;          // half <= 23 always (m <= 47)
    const float nf   = (float)n;
    const float mf   = (float)m;

    // ---- rows in registers: lane holds row `lane`; lanes<16 hold row lane+32.
    //      lane 31's (otherwise dead) r1 holds row 32 (delta-31 boundary patch).
    const float* cp = coords + (size_t)traj * 480;
    float r0[MD], r1[MD];
    {
        const float2* p0 = (const float2*)(cp + lane * MD);
#pragma unroll
        for (int k = 0; k < 5; k++) { float2 v = p0[k]; r0[2*k] = v.x; r0[2*k+1] = v.y; }
    }
#pragma unroll
    for (int k = 0; k < MD; k++) r1[k] = 0.f;
    if (lane < 16) {
        const float2* p1 = (const float2*)(cp + (lane + 32) * MD);
#pragma unroll
        for (int k = 0; k < 5; k++) { float2 v = p1[k]; r1[2*k] = v.x; r1[2*k+1] = v.y; }
    } else if (lane == 31) {
        const float2* p1 = (const float2*)(cp + 32 * MD);
#pragma unroll
        for (int k = 0; k < 5; k++) { float2 v = p1[k]; r1[2*k] = v.x; r1[2*k+1] = v.y; }
    }

    // ---- coord mean/var partials (lane31's r1 excluded: 63 < n never) ----
    float csum = 0.f, cssum = 0.f;
    if (lane < n) {
#pragma unroll
        for (int k = 0; k < MD; k++) { csum += r0[k]; cssum += r0[k] * r0[k]; }
    }
    if (lane + 32 < n) {
#pragma unroll
        for (int k = 0; k < MD; k++) { csum += r1[k]; cssum += r1[k] * r1[k]; }
    }

    // ---- total displacement: broadcast row0, owner lane accumulates ----
    const bool hiLast = (n > 32);
    const int  owner  = hiLast ? (n - 33) : (n - 1);
    float tdp_l = 0.f;
#pragma unroll
    for (int k = 0; k < MD; k++) {
        float f0 = __shfl_sync(FULLM, r0[k], 0);
        float lst = hiLast ? r1[k] : r0[k];
        float dd = lst - f0;
        tdp_l += dd * dd;
    }
    float tdp_s = (lane == owner) ? tdp_l : 0.f;

    // ---- deltas via shuffles ----
    const bool v0 = lane < m;           // delta i0 = lane
    const bool v1 = lane + 32 < m;      // delta i1 = lane + 32
    float d0[MD], d1[MD];
    float ss0 = 0.f, ss1 = 0.f;
#pragma unroll
    for (int k = 0; k < MD; k++) {
        float nx0 = __shfl_down_sync(FULLM, r0[k], 1);
        if (lane == 31) nx0 = r1[k];                  // row 32 from LDG
        float nx1 = __shfl_down_sync(FULLM, r1[k], 1);
        float a = v0 ? (nx0 - r0[k]) : 0.f;
        float b = v1 ? (nx1 - r1[k]) : 0.f;
        d0[k] = a; d1[k] = b;
        ss0 += a * a; ss1 += b * b;
    }
    float dmag0 = (ss0 > 0.f) ? sqrtf(fmaxf(ss0, 1e-30f)) : 0.f;
    float dmag1 = (ss1 > 0.f) ? sqrtf(fmaxf(ss1, 1e-30f)) : 0.f;
    float na0 = fmaxf(dmag0, 1e-8f), na1 = fmaxf(dmag1, 1e-8f);
    float rin0 = 1.0f / na0, rin1 = 1.0f / na1;

    // ---- dmag stats ----
    float fsum  = (lane < half + 1) ? dmag0 : 0.f;
    float shsum = ((lane >= half) && v0 ? dmag0 : 0.f) + dmag1;
    float dmsq  = ss0 + ss1;
    float maxdm = fmaxf(v0 ? dmag0 : -F_INF, v1 ? dmag1 : -F_INF);
    float dhalf = __shfl_sync(FULLM, dmag0, half);    // path = fsum+shsum-dhalf

    // ---- unit vectors + curvature dots ----
    float us[MD], uss = 0.f, dot0 = 0.f, dot1 = 0.f;
#pragma unroll
    for (int k = 0; k < MD; k++) {
        float u0 = d0[k] * rin0, u1 = d1[k] * rin1;
        us[k] = u0 + u1;
        uss += u0 * u0 + u1 * u1;
        float dn0 = __shfl_down_sync(FULLM, d0[k], 1);
        float c32 = __shfl_sync(FULLM, d1[k], 0);     // delta 32 (lane0's d1)
        if (lane == 31) dn0 = c32;
        float dn1 = __shfl_down_sync(FULLM, d1[k], 1);
        dot0 += d0[k] * dn0;
        dot1 += d1[k] * dn1;
    }
    float nan0 = __shfl_down_sync(FULLM, na0, 1);
    {
        float t = __shfl_sync(FULLM, na1, 0);
        if (lane == 31) nan0 = t;
    }
    float nan1 = __shfl_down_sync(FULLM, na1, 1);
    float cos0 = dot0 / (na0 * nan0);
    float cos1 = dot1 / (na1 * nan1);
    const bool c0 = lane < n - 2;
    const bool c1 = lane + 32 < n - 2;

    float cossum = (c0 ? cos0 : 0.f) + (c1 ? cos1 : 0.f);
    float cossq  = (c0 ? cos0 * cos0 : 0.f) + (c1 ? cos1 * cos1 : 0.f);
    float negmn  = fmaxf(c0 ? -cos0 : -F_INF, c1 ? -cos1 : -F_INF); // -mincos
    float maxcs  = fmaxf(c0 ? cos0 : -F_INF, c1 ? cos1 : -F_INF);
    float dirch  = ((c0 && cos0 < 0.f) ? 1.f : 0.f) + ((c1 && cos1 < 0.f) ? 1.f : 0.f);

    // ---- padded deltas / curvs ----
    if (lane < 3) {
#pragma unroll
        for (int k = 0; k < MD; k++) sfeat[w][21 + lane * MD + k] = d0[k];
    }
    if (lane < 9) sfeat[w][51 + lane] = c0 ? (1.0f - cos0) : 0.f;

    // ---- merged reduction trees ----
    // sums s0..s19: fsum,shsum,dmsq,uss,cossum,cossq,dirch,csum,cssum,tdp,us0..9
    float m0 = mrg(fsum,  shsum, 16, lane);
    float m1 = mrg(dmsq,  uss,   16, lane);
    float m2 = mrg(cossum,cossq, 16, lane);
    float m3 = mrg(dirch, csum,  16, lane);
    float m4 = mrg(cssum, tdp_s, 16, lane);
    float m5 = mrg(us[0], us[1], 16, lane);
    float m6 = mrg(us[2], us[3], 16, lane);
    float m7 = mrg(us[4], us[5], 16, lane);
    float m8 = mrg(us[6], us[7], 16, lane);
    float m9 = mrg(us[8], us[9], 16, lane);
    float n0 = mrg(m0, m1, 8, lane);
    float n1 = mrg(m2, m3, 8, lane);
    float n2 = mrg(m4, m5, 8, lane);
    float n3 = mrg(m6, m7, 8, lane);
    float n4 = mrg(m8, m9, 8, lane);
    float p0 = mrg(n0, n1, 4, lane);
    float p1 = mrg(n2, n3, 4, lane);
    n4 = solo(n4, 4);
    float q0 = mrg(p0, p1, 2, lane);
    n4 = solo(n4, 2);
    float rr = mrg(q0, n4, 1, lane);
    // lane map (k<16): 16*(k&1)+8*((k>>1)&1)+4*((k>>2)&1)+2*((k>>3)&1); (k>=16): +1 variant

    // max tree: maxdm -> lane0, maxcs -> lane16, -mincos -> lane8
    float t = mrgmax(maxdm, maxcs, 16, lane);
    t = mrgmax(t, negmn, 8, lane);
    t = solomax(t, 4); t = solomax(t, 2); t = solomax(t, 1);

    sred[w][lane]      = rr;
    sred[w][32 + lane] = t;
    __syncwarp();

    if (lane == 0) {
        const float* sr = sred[w];
        float s_fsum  = sr[0],  s_shsum = sr[16], s_dmsq = sr[8],  s_uss = sr[24];
        float s_cossum= sr[4],  s_cossq = sr[20], s_dirch= sr[12];
        float s_csum  = sr[28], s_cssum = sr[2],  s_tdp  = sr[18];
        float nsq = sr[10]*sr[10] + sr[26]*sr[26] + sr[6]*sr[6] + sr[22]*sr[22]
                  + sr[14]*sr[14] + sr[30]*sr[30] + sr[1]*sr[1] + sr[17]*sr[17]
                  + sr[9]*sr[9]   + sr[25]*sr[25];
        float s_maxdm = sr[32], s_maxcs = sr[48], s_mincs = -sr[40];

        float path = s_fsum + s_shsum - dhalf;
        float total_disp = (s_tdp > 0.f) ? sqrtf(fmaxf(s_tdp, 1e-30f)) : 0.f;
        float disp_ratio = total_disp / (path + F_EPS);
        float ncf = (float)(n - 2);
        float mean_cos  = s_cossum / ncf;
        float mean_curv = (ncf - s_cossum) / ncf;
        float max_curv  = 1.0f - s_mincs;
        float cvsq      = ncf - 2.0f * s_cossum + s_cossq;
        float curv_var  = (cvsq - ncf * mean_curv * mean_curv) / fmaxf(ncf - 1.f, 1.f);
        float std_curv  = (ncf > 1.f) ? sqrtf(fmaxf(curv_var, 1e-30f)) : 0.f;
        float curv_range = s_maxcs - s_mincs;
        float dir_chg   = s_dirch / fmaxf(ncf, 1.f);
        float loop_score = 1.f - total_disp / (path + F_EPS);
        float fh = s_fsum / (float)(half + 1);
        float sh = s_shsum / (float)(m - half);
        float conv = (fh - sh) / (fh + F_EPS);
        float casc = (sh - fh) / (fh + F_EPS);
        float npairs = mf * (mf - 1.f) * 0.5f;
        float par = 0.5f * (nsq - s_uss) / fmaxf(npairs, 1.f);
        float mean_dm = path / mf;
        float dm_var  = (s_dmsq - mf * mean_dm * mean_dm) / fmaxf(mf - 1.f, 1.f);
        float std_dm  = (mf > 1.f) ? sqrtf(fmaxf(dm_var, 1e-30f)) : 0.f;
        float jump = (mean_dm > F_EPS) ? s_maxdm / mean_dm : 1.f;
        float cnt  = nf * (float)MD;
        float mc   = s_csum / cnt;
        float cvar = (s_cssum - cnt * mc * mc) / (cnt - 1.f);
        float stdc = sqrtf(fmaxf(cvar, 1e-30f));

        float* sf = sfeat[w];
        sf[0]  = total_disp;  sf[1]  = path;        sf[2]  = disp_ratio;
        sf[3]  = nf * 0.1f;   sf[4]  = mean_curv;   sf[5]  = max_curv;
        sf[6]  = std_curv;    sf[7]  = curv_range;  sf[8]  = mean_cos;
        sf[9]  = s_mincs;     sf[10] = dir_chg;     sf[11] = disp_ratio;
        sf[12] = loop_score;  sf[13] = conv;        sf[14] = par;
        sf[15] = jump;        sf[16] = casc;        sf[17] = mean_dm;
        sf[18] = std_dm;      sf[19] = mc;          sf[20] = stdc;
    }
    __syncwarp();

    float* gout = g_feats + (size_t)traj * 64;
    if (lane < 30) {
        gout[lane]      = sfeat[w][lane];
        gout[30 + lane] = sfeat[w][30 + lane];
    }
}

// --------------------- K2: GEMM + LayerNorm + GELU --------------------------
__device__ __forceinline__ unsigned long long pk2(float a, float b) {
    unsigned long long r;
    asm("mov.b64 %0, {%1, %2};" : "=l"(r) : "f"(a), "f"(b));
    return r;
}
__device__ __forceinline__ void upk2(unsigned long long v, float& a, float& b) {
    asm("mov.b64 {%0, %1}, %2;" : "=f"(a), "=f"(b) : "l"(v));
}
__device__ __forceinline__ unsigned long long fma2(unsigned long long a,
                                                   unsigned long long b,
                                                   unsigned long long c) {
    unsigned long long d;
    asm("fma.rn.f32x2 %0, %1, %2, %3;" : "=l"(d) : "l"(a), "l"(b), "l"(c));
    return d;
}

__global__ void __launch_bounds__(128)
k2_head(const float* __restrict__ Wg, const float* __restrict__ bg,
        const float* __restrict__ lnwg, const float* __restrict__ lnbg,
        float* __restrict__ out, int B)
{
    __shared__ float sW[NF * H];          // 11.25 KB
    __shared__ float sfe[TB * 61];        // 15.25 KB

    const int tid = threadIdx.x;
    const int t0  = blockIdx.x * TB;

    for (int i = tid; i < NF * H; i += 128) sW[i] = Wg[i];
    for (int i = tid; i < TB * NF; i += 128) {
        int r = i / NF, f = i - r * NF;
        sfe[r * 61 + f] = g_feats[(size_t)(t0 + r) * 64 + f];
    }
    __syncthreads();

    const int tx = tid & 7;               // 8 column groups of 6
    const int ty = tid >> 3;              // 16 row groups of 4
    const int colb = tx * 6;

    unsigned long long acc[4][3];
    {
        unsigned long long b0 = pk2(bg[colb + 0], bg[colb + 1]);
        unsigned long long b1 = pk2(bg[colb + 2], bg[colb + 3]);
        unsigned long long b2 = pk2(bg[colb + 4], bg[colb + 5]);
#pragma unroll
        for (int r = 0; r < 4; r++) { acc[r][0] = b0; acc[r][1] = b1; acc[r][2] = b2; }
    }

    const float* fbase = sfe + ty * 4 * 61;
#pragma unroll 4
    for (int f = 0; f < NF; f++) {
        unsigned long long w0 = *(const unsigned long long*)(sW + f * H + colb);
        unsigned long long w1 = *(const unsigned long long*)(sW + f * H + colb + 2);
        unsigned long long w2 = *(const unsigned long long*)(sW + f * H + colb + 4);
#pragma unroll
        for (int r = 0; r < 4; r++) {
            float fv = fbase[r * 61 + f];
            unsigned long long fp = pk2(fv, fv);
            acc[r][0] = fma2(fp, w0, acc[r][0]);
            acc[r][1] = fma2(fp, w1, acc[r][1]);
            acc[r][2] = fma2(fp, w2, acc[r][2]);
        }
    }

    float lw[6], lb[6];
#pragma unroll
    for (int c = 0; c < 6; c++) { lw[c] = lnwg[colb + c]; lb[c] = lnbg[colb + c]; }

#pragma unroll
    for (int r = 0; r < 4; r++) {
        float x[6];
        upk2(acc[r][0], x[0], x[1]);
        upk2(acc[r][1], x[2], x[3]);
        upk2(acc[r][2], x[4], x[5]);
        float s = 0.f, sq = 0.f;
#pragma unroll
        for (int c = 0; c < 6; c++) { s += x[c]; sq += x[c] * x[c]; }
#pragma unroll
        for (int o = 1; o < 8; o <<= 1) {
            s  += __shfl_xor_sync(FULLM, s,  o);
            sq += __shfl_xor_sync(FULLM, sq, o);
        }
        float mu  = s * (1.0f / 48.0f);
        float var = sq * (1.0f / 48.0f) - mu * mu;
        float inv = rsqrtf(var + 1e-5f);

        int row = t0 + ty * 4 + r;
        if (row < B) {
            float y[6];
#pragma unroll
            for (int c = 0; c < 6; c++) {
                float v = (x[c] - mu) * inv * lw[c] + lb[c];
                y[c] = 0.5f * v * (1.0f + erff(v * 0.70710678118654752f));
            }
            float* op = out + (size_t)row * H + colb;
            *(float2*)(op + 0) = make_float2(y[0], y[1]);
            *(float2*)(op + 2) = make_float2(y[2], y[3]);
            *(float2*)(op + 4) = make_float2(y[4], y[5]);
        }
    }
}

extern "C" void kernel_launch(void* const* d_in, const int* in_sizes, int n_in,
                              void* d_out, int out_size) {
    const float* coords  = (const float*)d_in[0];
    const int*   lengths = (const int*)d_in[1];
    const float* W       = (const float*)d_in[2];
    const float* b       = (const float*)d_in[3];
    const float* lnw     = (const float*)d_in[4];
    const float* lnb     = (const float*)d_in[5];
    float* out = (float*)d_out;

    int B = in_sizes[1];
    int g1 = (B + WPB - 1) / WPB;
    k1_features<<<g1, TPB1>>>(coords, lengths, B);
    int g2 = (B + TB - 1) / TB;
    k2_head<<<g2, 128>>>(W, b, lnw, lnb, out, B);
}

// round 4
// speedup vs baseline: 1.5091x; 1.0432x over previous
#include <cuda_runtime.h>
#include <math.h>

#define F_EPS 1e-9f
#define F_INF __int_as_float(0x7f800000)

constexpr int MD   = 10;
constexpr int WPB  = 4;            // warps (trajectories) per block in K1
constexpr int TPB1 = WPB * 32;
constexpr int TB   = 32;           // trajectories per block in K2
constexpr int H    = 48;
constexpr int NF   = 60;

// scratch: feats padded to stride 64 (max 65536 trajectories)
__device__ float g_feats[65536 * 64];

#define FULLM 0xffffffffu

// merge-reduce: one shuffle advances TWO accumulators one level.
// x's reduction lands on lanes with `bit` clear, y's on lanes with `bit` set.
__device__ __forceinline__ float mrg(float x, float y, int bit, int lane) {
    float sel = (lane & bit) ? x : y;
    float rec = __shfl_xor_sync(FULLM, sel, bit);
    return (lane & bit) ? (y + rec) : (x + rec);
}
__device__ __forceinline__ float mrgmax(float x, float y, int bit, int lane) {
    float sel = (lane & bit) ? x : y;
    float rec = __shfl_xor_sync(FULLM, sel, bit);
    return (lane & bit) ? fmaxf(y, rec) : fmaxf(x, rec);
}
__device__ __forceinline__ float solo(float x, int bit) {
    return x + __shfl_xor_sync(FULLM, x, bit);
}
__device__ __forceinline__ float solomax(float x, int bit) {
    return fmaxf(x, __shfl_xor_sync(FULLM, x, bit));
}

// ------------------------------- K1: features -------------------------------
__global__ void __launch_bounds__(TPB1, 6)
k1_features(const float* __restrict__ coords, const int* __restrict__ lengths, int B)
{
    __shared__ alignas(16) float sfeat[WPB][NF];
    __shared__ float sred[WPB][64];

    const int w    = threadIdx.x >> 5;
    const int lane = threadIdx.x & 31;
    const int traj = blockIdx.x * WPB + w;
    if (traj >= B) return;

    const int   n    = lengths[traj];
    const int   m    = n - 1;
    const int   half = m >> 1;          // half <= 23 always (m <= 47)
    const float nf   = (float)n;
    const float mf   = (float)m;

    // ---- rows in registers: lane holds row `lane`; lanes<16 hold row lane+32.
    //      lane 31's (otherwise dead) r1 holds row 32 (delta-31 boundary patch).
    const float* cp = coords + (size_t)traj * 480;
    float r0[MD], r1[MD];
    {
        const float2* p0 = (const float2*)(cp + lane * MD);
#pragma unroll
        for (int k = 0; k < 5; k++) { float2 v = p0[k]; r0[2*k] = v.x; r0[2*k+1] = v.y; }
    }
#pragma unroll
    for (int k = 0; k < MD; k++) r1[k] = 0.f;
    if (lane < 16) {
        const float2* p1 = (const float2*)(cp + (lane + 32) * MD);
#pragma unroll
        for (int k = 0; k < 5; k++) { float2 v = p1[k]; r1[2*k] = v.x; r1[2*k+1] = v.y; }
    } else if (lane == 31) {
        const float2* p1 = (const float2*)(cp + 32 * MD);
#pragma unroll
        for (int k = 0; k < 5; k++) { float2 v = p1[k]; r1[2*k] = v.x; r1[2*k+1] = v.y; }
    }

    // ---- coord mean/var partials (lane31's r1 excluded: 63 < n never) ----
    float csum = 0.f, cssum = 0.f;
    if (lane < n) {
#pragma unroll
        for (int k = 0; k < MD; k++) { csum += r0[k]; cssum += r0[k] * r0[k]; }
    }
    if (lane + 32 < n) {
#pragma unroll
        for (int k = 0; k < MD; k++) { csum += r1[k]; cssum += r1[k] * r1[k]; }
    }

    // ---- total displacement: broadcast row0, owner lane accumulates ----
    const bool hiLast = (n > 32);
    const int  owner  = hiLast ? (n - 33) : (n - 1);
    float tdp_l = 0.f;
#pragma unroll
    for (int k = 0; k < MD; k++) {
        float f0 = __shfl_sync(FULLM, r0[k], 0);
        float lst = hiLast ? r1[k] : r0[k];
        float dd = lst - f0;
        tdp_l += dd * dd;
    }
    float tdp_s = (lane == owner) ? tdp_l : 0.f;

    // ---- deltas via shuffles ----
    const bool v0 = lane < m;           // delta i0 = lane
    const bool v1 = lane + 32 < m;      // delta i1 = lane + 32
    float d0[MD], d1[MD];
    float ss0 = 0.f, ss1 = 0.f;
#pragma unroll
    for (int k = 0; k < MD; k++) {
        float nx0 = __shfl_down_sync(FULLM, r0[k], 1);
        if (lane == 31) nx0 = r1[k];                  // row 32 from LDG
        float nx1 = __shfl_down_sync(FULLM, r1[k], 1);
        float a = v0 ? (nx0 - r0[k]) : 0.f;
        float b = v1 ? (nx1 - r1[k]) : 0.f;
        d0[k] = a; d1[k] = b;
        ss0 += a * a; ss1 += b * b;
    }
    float dmag0 = (ss0 > 0.f) ? sqrtf(fmaxf(ss0, 1e-30f)) : 0.f;
    float dmag1 = (ss1 > 0.f) ? sqrtf(fmaxf(ss1, 1e-30f)) : 0.f;
    float na0 = fmaxf(dmag0, 1e-8f), na1 = fmaxf(dmag1, 1e-8f);
    float rin0 = 1.0f / na0, rin1 = 1.0f / na1;

    // ---- dmag stats ----
    float fsum  = (lane < half + 1) ? dmag0 : 0.f;
    float shsum = ((lane >= half) && v0 ? dmag0 : 0.f) + dmag1;
    float dmsq  = ss0 + ss1;
    float maxdm = fmaxf(v0 ? dmag0 : -F_INF, v1 ? dmag1 : -F_INF);
    float dhalf = __shfl_sync(FULLM, dmag0, half);    // path = fsum+shsum-dhalf

    // ---- unit vectors + curvature dots ----
    float us[MD], uss = 0.f, dot0 = 0.f, dot1 = 0.f;
#pragma unroll
    for (int k = 0; k < MD; k++) {
        float u0 = d0[k] * rin0, u1 = d1[k] * rin1;
        us[k] = u0 + u1;
        uss += u0 * u0 + u1 * u1;
        float dn0 = __shfl_down_sync(FULLM, d0[k], 1);
        float c32 = __shfl_sync(FULLM, d1[k], 0);     // delta 32 (lane0's d1)
        if (lane == 31) dn0 = c32;
        float dn1 = __shfl_down_sync(FULLM, d1[k], 1);
        dot0 += d0[k] * dn0;
        dot1 += d1[k] * dn1;
    }
    // cos via reciprocal products (no IEEE div)
    float rinn0 = __shfl_down_sync(FULLM, rin0, 1);
    {
        float t = __shfl_sync(FULLM, rin1, 0);
        if (lane == 31) rinn0 = t;
    }
    float rinn1 = __shfl_down_sync(FULLM, rin1, 1);
    float cos0 = dot0 * rin0 * rinn0;
    float cos1 = dot1 * rin1 * rinn1;
    const bool c0 = lane < n - 2;
    const bool c1 = lane + 32 < n - 2;

    float cossum = (c0 ? cos0 : 0.f) + (c1 ? cos1 : 0.f);
    float cossq  = (c0 ? cos0 * cos0 : 0.f) + (c1 ? cos1 * cos1 : 0.f);
    float negmn  = fmaxf(c0 ? -cos0 : -F_INF, c1 ? -cos1 : -F_INF); // -mincos
    float maxcs  = fmaxf(c0 ? cos0 : -F_INF, c1 ? cos1 : -F_INF);
    float dirch  = ((c0 && cos0 < 0.f) ? 1.f : 0.f) + ((c1 && cos1 < 0.f) ? 1.f : 0.f);

    // ---- padded deltas / curvs ----
    if (lane < 3) {
#pragma unroll
        for (int k = 0; k < MD; k++) sfeat[w][21 + lane * MD + k] = d0[k];
    }
    if (lane < 9) sfeat[w][51 + lane] = c0 ? (1.0f - cos0) : 0.f;

    // ---- merged reduction trees ----
    float m0 = mrg(fsum,  shsum, 16, lane);
    float m1 = mrg(dmsq,  uss,   16, lane);
    float m2 = mrg(cossum,cossq, 16, lane);
    float m3 = mrg(dirch, csum,  16, lane);
    float m4 = mrg(cssum, tdp_s, 16, lane);
    float m5 = mrg(us[0], us[1], 16, lane);
    float m6 = mrg(us[2], us[3], 16, lane);
    float m7 = mrg(us[4], us[5], 16, lane);
    float m8 = mrg(us[6], us[7], 16, lane);
    float m9 = mrg(us[8], us[9], 16, lane);
    float n0 = mrg(m0, m1, 8, lane);
    float n1 = mrg(m2, m3, 8, lane);
    float n2 = mrg(m4, m5, 8, lane);
    float n3 = mrg(m6, m7, 8, lane);
    float n4 = mrg(m8, m9, 8, lane);
    float p0 = mrg(n0, n1, 4, lane);
    float p1 = mrg(n2, n3, 4, lane);
    n4 = solo(n4, 4);
    float q0 = mrg(p0, p1, 2, lane);
    n4 = solo(n4, 2);
    float rr = mrg(q0, n4, 1, lane);

    // max tree (FIXED): negmn reduced over bit16 BEFORE entering at bit8.
    float t = mrgmax(maxdm, maxcs, 16, lane);    // maxdm -> bit16=0, maxcs -> bit16=1
    float u = solomax(negmn, 16);                // negmn covers bit16
    t = mrgmax(t, u, 8, lane);                   // negmn -> bit8=1 lanes
    t = solomax(t, 4); t = solomax(t, 2); t = solomax(t, 1);
    // maxdm -> lane 0 (sr[32]); maxcs -> lane 16 (sr[48]); negmn -> lane 8 (sr[40])

    sred[w][lane]      = rr;
    sred[w][32 + lane] = t;
    __syncwarp();

    if (lane == 0) {
        const float* sr = sred[w];
        float s_fsum  = sr[0],  s_shsum = sr[16], s_dmsq = sr[8],  s_uss = sr[24];
        float s_cossum= sr[4],  s_cossq = sr[20], s_dirch= sr[12];
        float s_csum  = sr[28], s_cssum = sr[2],  s_tdp  = sr[18];
        float nsq = sr[10]*sr[10] + sr[26]*sr[26] + sr[6]*sr[6] + sr[22]*sr[22]
                  + sr[14]*sr[14] + sr[30]*sr[30] + sr[1]*sr[1] + sr[17]*sr[17]
                  + sr[9]*sr[9]   + sr[25]*sr[25];
        float s_maxdm = sr[32], s_maxcs = sr[48], s_mincs = -sr[40];

        float path = s_fsum + s_shsum - dhalf;
        float total_disp = (s_tdp > 0.f) ? sqrtf(fmaxf(s_tdp, 1e-30f)) : 0.f;
        float disp_ratio = __fdividef(total_disp, path + F_EPS);
        float loop_score = 1.f - disp_ratio;
        float ncf  = (float)(n - 2);
        float rncf = __fdividef(1.f, ncf);
        float mean_cos  = s_cossum * rncf;
        float mean_curv = 1.f - mean_cos;
        float max_curv  = 1.0f - s_mincs;
        float cvsq      = ncf - 2.0f * s_cossum + s_cossq;
        float curv_var  = (cvsq - ncf * mean_curv * mean_curv)
                          * __fdividef(1.f, fmaxf(ncf - 1.f, 1.f));
        float std_curv  = (ncf > 1.f) ? sqrtf(fmaxf(curv_var, 1e-30f)) : 0.f;
        float curv_range = s_maxcs - s_mincs;
        float dir_chg   = s_dirch * rncf;        // ncf >= 2 always (n >= 4)
        float fh = s_fsum  * __fdividef(1.f, (float)(half + 1));
        float sh = s_shsum * __fdividef(1.f, (float)(m - half));
        float conv = __fdividef(fh - sh, fh + F_EPS);
        float casc = -conv;
        float npairs = mf * (mf - 1.f) * 0.5f;
        float par = 0.5f * (nsq - s_uss) * __fdividef(1.f, fmaxf(npairs, 1.f));
        float rmf = __fdividef(1.f, mf);
        float mean_dm = path * rmf;
        float dm_var  = (s_dmsq - mf * mean_dm * mean_dm)
                        * __fdividef(1.f, fmaxf(mf - 1.f, 1.f));
        float std_dm  = sqrtf(fmaxf(dm_var, 1e-30f));   // mf >= 3 always
        float jump = (mean_dm > F_EPS) ? __fdividef(s_maxdm, mean_dm) : 1.f;
        float cnt  = nf * (float)MD;
        float mc   = s_csum * __fdividef(1.f, cnt);
        float cvar = (s_cssum - cnt * mc * mc) * __fdividef(1.f, cnt - 1.f);
        float stdc = sqrtf(fmaxf(cvar, 1e-30f));

        float* sf = sfeat[w];
        sf[0]  = total_disp;  sf[1]  = path;        sf[2]  = disp_ratio;
        sf[3]  = nf * 0.1f;   sf[4]  = mean_curv;   sf[5]  = max_curv;
        sf[6]  = std_curv;    sf[7]  = curv_range;  sf[8]  = mean_cos;
        sf[9]  = s_mincs;     sf[10] = dir_chg;     sf[11] = disp_ratio;
        sf[12] = loop_score;  sf[13] = conv;        sf[14] = par;
        sf[15] = jump;        sf[16] = casc;        sf[17] = mean_dm;
        sf[18] = std_dm;      sf[19] = mc;          sf[20] = stdc;
    }
    __syncwarp();

    if (lane < 15) {
        float4 v = *(const float4*)&sfeat[w][lane * 4];
        *(float4*)(g_feats + (size_t)traj * 64 + lane * 4) = v;
    }
}

// --------------------- K2: GEMM + LayerNorm + GELU --------------------------
__device__ __forceinline__ unsigned long long pk2(float a, float b) {
    unsigned long long r;
    asm("mov.b64 %0, {%1, %2};" : "=l"(r) : "f"(a), "f"(b));
    return r;
}
__device__ __forceinline__ void upk2(unsigned long long v, float& a, float& b) {
    asm("mov.b64 {%0, %1}, %2;" : "=f"(a), "=f"(b) : "l"(v));
}
__device__ __forceinline__ unsigned long long fma2(unsigned long long a,
                                                   unsigned long long b,
                                                   unsigned long long c) {
    unsigned long long d;
    asm("fma.rn.f32x2 %0, %1, %2, %3;" : "=l"(d) : "l"(a), "l"(b), "l"(c));
    return d;
}

__global__ void __launch_bounds__(128)
k2_head(const float* __restrict__ Wg, const float* __restrict__ bg,
        const float* __restrict__ lnwg, const float* __restrict__ lnbg,
        float* __restrict__ out, int B)
{
    __shared__ float4 sW4[NF * H / 4];    // 11.25 KB
    __shared__ float sfe[TB * 61];        // 7.6 KB
    float* sW = (float*)sW4;

    const int tid = threadIdx.x;
    const int t0  = blockIdx.x * TB;

    for (int i = tid; i < NF * H / 4; i += 128) sW4[i] = ((const float4*)Wg)[i];
    for (int i = tid; i < TB * NF; i += 128) {
        int r = i / NF, f = i - r * NF;
        sfe[r * 61 + f] = g_feats[(size_t)(t0 + r) * 64 + f];
    }
    __syncthreads();

    const int tx = tid & 7;               // 8 column groups of 6
    const int ty = tid >> 3;              // 16 row groups of 2
    const int colb = tx * 6;

    unsigned long long acc[2][3];
    {
        unsigned long long b0 = pk2(bg[colb + 0], bg[colb + 1]);
        unsigned long long b1 = pk2(bg[colb + 2], bg[colb + 3]);
        unsigned long long b2 = pk2(bg[colb + 4], bg[colb + 5]);
#pragma unroll
        for (int r = 0; r < 2; r++) { acc[r][0] = b0; acc[r][1] = b1; acc[r][2] = b2; }
    }

    const float* fbase = sfe + ty * 2 * 61;
#pragma unroll 5
    for (int f = 0; f < NF; f++) {
        unsigned long long w0 = *(const unsigned long long*)(sW + f * H + colb);
        unsigned long long w1 = *(const unsigned long long*)(sW + f * H + colb + 2);
        unsigned long long w2 = *(const unsigned long long*)(sW + f * H + colb + 4);
#pragma unroll
        for (int r = 0; r < 2; r++) {
            float fv = fbase[r * 61 + f];
            unsigned long long fp = pk2(fv, fv);
            acc[r][0] = fma2(fp, w0, acc[r][0]);
            acc[r][1] = fma2(fp, w1, acc[r][1]);
            acc[r][2] = fma2(fp, w2, acc[r][2]);
        }
    }

    float lw[6], lb[6];
#pragma unroll
    for (int c = 0; c < 6; c++) { lw[c] = lnwg[colb + c]; lb[c] = lnbg[colb + c]; }

#pragma unroll
    for (int r = 0; r < 2; r++) {
        float x[6];
        upk2(acc[r][0], x[0], x[1]);
        upk2(acc[r][1], x[2], x[3]);
        upk2(acc[r][2], x[4], x[5]);
        float s = 0.f, sq = 0.f;
#pragma unroll
        for (int c = 0; c < 6; c++) { s += x[c]; sq += x[c] * x[c]; }
#pragma unroll
        for (int o = 1; o < 8; o <<= 1) {
            s  += __shfl_xor_sync(FULLM, s,  o);
            sq += __shfl_xor_sync(FULLM, sq, o);
        }
        float mu  = s * (1.0f / 48.0f);
        float var = sq * (1.0f / 48.0f) - mu * mu;
        float inv = rsqrtf(var + 1e-5f);

        int row = t0 + ty * 2 + r;
        if (row < B) {
            float y[6];
#pragma unroll
            for (int c = 0; c < 6; c++) {
                float v = (x[c] - mu) * inv * lw[c] + lb[c];
                y[c] = 0.5f * v * (1.0f + erff(v * 0.70710678118654752f));
            }
            float* op = out + (size_t)row * H + colb;
            *(float2*)(op + 0) = make_float2(y[0], y[1]);
            *(float2*)(op + 2) = make_float2(y[2], y[3]);
            *(float2*)(op + 4) = make_float2(y[4], y[5]);
        }
    }
}

extern "C" void kernel_launch(void* const* d_in, const int* in_sizes, int n_in,
                              void* d_out, int out_size) {
    const float* coords  = (const float*)d_in[0];
    const int*   lengths = (const int*)d_in[1];
    const float* W       = (const float*)d_in[2];
    const float* b       = (const float*)d_in[3];
    const float* lnw     = (const float*)d_in[4];
    const float* lnb     = (const float*)d_in[5];
    float* out = (float*)d_out;

    int B = in_sizes[1];
    int g1 = (B + WPB - 1) / WPB;
    k1_features<<<g1, TPB1>>>(coords, lengths, B);
    int g2 = (B + TB - 1) / TB;
    k2_head<<<g2, 128>>>(W, b, lnw, lnb, out, B);
}

// round 5
// speedup vs baseline: 1.5186x; 1.0063x over previous
#include <cuda_runtime.h>
#include <math.h>

#define F_EPS 1e-9f
#define F_INF __int_as_float(0x7f800000)

constexpr int MD   = 10;
constexpr int WPB  = 4;            // warps (trajectories) per block in K1
constexpr int TPB1 = WPB * 32;
constexpr int TB   = 64;           // trajectories per block in K2
constexpr int H    = 48;
constexpr int NF   = 60;

// scratch: feats padded to stride 64 (max 65536 trajectories)
__device__ float g_feats[65536 * 64];

#define FULLM 0xffffffffu

// merge-reduce: one shuffle advances TWO accumulators one level.
__device__ __forceinline__ float mrg(float x, float y, int bit, int lane) {
    float sel = (lane & bit) ? x : y;
    float rec = __shfl_xor_sync(FULLM, sel, bit);
    return (lane & bit) ? (y + rec) : (x + rec);
}
__device__ __forceinline__ float mrgmax(float x, float y, int bit, int lane) {
    float sel = (lane & bit) ? x : y;
    float rec = __shfl_xor_sync(FULLM, sel, bit);
    return (lane & bit) ? fmaxf(y, rec) : fmaxf(x, rec);
}
__device__ __forceinline__ float solo(float x, int bit) {
    return x + __shfl_xor_sync(FULLM, x, bit);
}
__device__ __forceinline__ float solomax(float x, int bit) {
    return fmaxf(x, __shfl_xor_sync(FULLM, x, bit));
}

// ------------------------------- K1: features -------------------------------
__global__ void __launch_bounds__(TPB1, 7)
k1_features(const float* __restrict__ coords, const int* __restrict__ lengths, int B)
{
    __shared__ alignas(16) float sfeat[WPB][NF];
    __shared__ float sred[WPB][64];

    const int w    = threadIdx.x >> 5;
    const int lane = threadIdx.x & 31;
    const int traj = blockIdx.x * WPB + w;
    if (traj >= B) return;

    const int   n    = lengths[traj];
    const int   m    = n - 1;
    const int   half = m >> 1;          // half <= 23 always (m <= 47)
    const float nf   = (float)n;
    const float mf   = (float)m;

    // ---- rows in registers: lane holds row `lane`; lanes<16 hold row lane+32.
    //      lane 31's (otherwise dead) r1 holds row 32 (delta-31 boundary patch).
    const float* cp = coords + (size_t)traj * 480;
    float r0[MD], r1[MD];
    {
        const float2* p0 = (const float2*)(cp + lane * MD);
#pragma unroll
        for (int k = 0; k < 5; k++) { float2 v = p0[k]; r0[2*k] = v.x; r0[2*k+1] = v.y; }
    }
#pragma unroll
    for (int k = 0; k < MD; k++) r1[k] = 0.f;
    if (lane < 16) {
        const float2* p1 = (const float2*)(cp + (lane + 32) * MD);
#pragma unroll
        for (int k = 0; k < 5; k++) { float2 v = p1[k]; r1[2*k] = v.x; r1[2*k+1] = v.y; }
    } else if (lane == 31) {
        const float2* p1 = (const float2*)(cp + 32 * MD);
#pragma unroll
        for (int k = 0; k < 5; k++) { float2 v = p1[k]; r1[2*k] = v.x; r1[2*k+1] = v.y; }
    }

    // ---- coord mean/var partials (lane31's r1 excluded: 63 < n never) ----
    float csum = 0.f, cssum = 0.f;
    if (lane < n) {
#pragma unroll
        for (int k = 0; k < MD; k++) { csum += r0[k]; cssum += r0[k] * r0[k]; }
    }
    if (lane + 32 < n) {
#pragma unroll
        for (int k = 0; k < MD; k++) { csum += r1[k]; cssum += r1[k] * r1[k]; }
    }

    // ---- total displacement: broadcast row0, owner lane accumulates ----
    const bool hiLast = (n > 32);
    const int  owner  = hiLast ? (n - 33) : (n - 1);
    float tdp_l = 0.f;
#pragma unroll
    for (int k = 0; k < MD; k++) {
        float f0 = __shfl_sync(FULLM, r0[k], 0);
        float lst = hiLast ? r1[k] : r0[k];
        float dd = lst - f0;
        tdp_l += dd * dd;
    }
    float tdp_s = (lane == owner) ? tdp_l : 0.f;

    // ---- deltas via shuffles ----
    const bool v0 = lane < m;           // delta i0 = lane
    const bool v1 = lane + 32 < m;      // delta i1 = lane + 32
    float d0[MD], d1[MD];
    float ss0 = 0.f, ss1 = 0.f;
#pragma unroll
    for (int k = 0; k < MD; k++) {
        float nx0 = __shfl_down_sync(FULLM, r0[k], 1);
        if (lane == 31) nx0 = r1[k];                  // row 32 from LDG
        float nx1 = __shfl_down_sync(FULLM, r1[k], 1);
        float a = v0 ? (nx0 - r0[k]) : 0.f;
        float b = v1 ? (nx1 - r1[k]) : 0.f;
        d0[k] = a; d1[k] = b;
        ss0 += a * a; ss1 += b * b;
    }
    float dmag0 = (ss0 > 0.f) ? sqrtf(fmaxf(ss0, 1e-30f)) : 0.f;
    float dmag1 = (ss1 > 0.f) ? sqrtf(fmaxf(ss1, 1e-30f)) : 0.f;
    float na0 = fmaxf(dmag0, 1e-8f), na1 = fmaxf(dmag1, 1e-8f);
    float rin0 = 1.0f / na0, rin1 = 1.0f / na1;

    // ---- dmag stats ----
    float fsum  = (lane < half + 1) ? dmag0 : 0.f;
    float shsum = ((lane >= half) && v0 ? dmag0 : 0.f) + dmag1;
    float dmsq  = ss0 + ss1;
    float maxdm = fmaxf(v0 ? dmag0 : -F_INF, v1 ? dmag1 : -F_INF);
    float dhalf = __shfl_sync(FULLM, dmag0, half);    // path = fsum+shsum-dhalf

    // ---- unit-vector pass (before lane31 overwrites d1) ----
    float us[MD], uss = 0.f;
#pragma unroll
    for (int k = 0; k < MD; k++) {
        float u0 = d0[k] * rin0, u1 = d1[k] * rin1;
        us[k] = u0 + u1;
        uss += u0 * u0 + u1 * u1;
    }

    // ---- lane 31 builds delta-32 locally (rows 32,33 from GMEM) ----
    float rin32 = 0.f;
    if (lane == 31) {
        const float2* p2 = (const float2*)(cp + 33 * MD);
        float ssl = 0.f;
#pragma unroll
        for (int k = 0; k < 5; k++) {
            float2 v = p2[k];
            float a = v.x - r1[2*k];
            float b = v.y - r1[2*k+1];
            d1[2*k] = a; d1[2*k+1] = b;
            ssl += a * a + b * b;
        }
        float dm = (ssl > 0.f) ? sqrtf(fmaxf(ssl, 1e-30f)) : 0.f;
        rin32 = 1.0f / fmaxf(dm, 1e-8f);
    }

    // ---- curvature dot pass (2 shuffles per k) ----
    float dot0 = 0.f, dot1 = 0.f;
#pragma unroll
    for (int k = 0; k < MD; k++) {
        float dn0 = __shfl_down_sync(FULLM, d0[k], 1);
        if (lane == 31) dn0 = d1[k];                  // local delta 32
        float dn1 = __shfl_down_sync(FULLM, d1[k], 1);
        dot0 += d0[k] * dn0;
        dot1 += d1[k] * dn1;
    }
    float rinn0 = __shfl_down_sync(FULLM, rin0, 1);
    if (lane == 31) rinn0 = rin32;
    float rinn1 = __shfl_down_sync(FULLM, rin1, 1);
    float cos0 = dot0 * rin0 * rinn0;
    float cos1 = dot1 * rin1 * rinn1;
    const bool c0 = lane < n - 2;
    const bool c1 = lane + 32 < n - 2;

    float cossum = (c0 ? cos0 : 0.f) + (c1 ? cos1 : 0.f);
    float cossq  = (c0 ? cos0 * cos0 : 0.f) + (c1 ? cos1 * cos1 : 0.f);
    float negmn  = fmaxf(c0 ? -cos0 : -F_INF, c1 ? -cos1 : -F_INF); // -mincos
    float maxcs  = fmaxf(c0 ? cos0 : -F_INF, c1 ? cos1 : -F_INF);
    float dirch  = ((c0 && cos0 < 0.f) ? 1.f : 0.f) + ((c1 && cos1 < 0.f) ? 1.f : 0.f);

    // ---- padded deltas / curvs ----
    if (lane < 3) {
#pragma unroll
        for (int k = 0; k < MD; k++) sfeat[w][21 + lane * MD + k] = d0[k];
    }
    if (lane < 9) sfeat[w][51 + lane] = c0 ? (1.0f - cos0) : 0.f;

    // ---- merged reduction trees ----
    float m0 = mrg(fsum,  shsum, 16, lane);
    float m1 = mrg(dmsq,  uss,   16, lane);
    float m2 = mrg(cossum,cossq, 16, lane);
    float m3 = mrg(dirch, csum,  16, lane);
    float m4 = mrg(cssum, tdp_s, 16, lane);
    float m5 = mrg(us[0], us[1], 16, lane);
    float m6 = mrg(us[2], us[3], 16, lane);
    float m7 = mrg(us[4], us[5], 16, lane);
    float m8 = mrg(us[6], us[7], 16, lane);
    float m9 = mrg(us[8], us[9], 16, lane);
    float n0 = mrg(m0, m1, 8, lane);
    float n1 = mrg(m2, m3, 8, lane);
    float n2 = mrg(m4, m5, 8, lane);
    float n3 = mrg(m6, m7, 8, lane);
    float n4 = mrg(m8, m9, 8, lane);
    float p0 = mrg(n0, n1, 4, lane);
    float p1 = mrg(n2, n3, 4, lane);
    n4 = solo(n4, 4);
    float q0 = mrg(p0, p1, 2, lane);
    n4 = solo(n4, 2);
    float rr = mrg(q0, n4, 1, lane);

    // max tree: negmn reduced over bit16 BEFORE entering at bit8.
    float t = mrgmax(maxdm, maxcs, 16, lane);
    float u = solomax(negmn, 16);
    t = mrgmax(t, u, 8, lane);
    t = solomax(t, 4); t = solomax(t, 2); t = solomax(t, 1);

    sred[w][lane]      = rr;
    sred[w][32 + lane] = t;
    __syncwarp();

    if (lane == 0) {
        const float* sr = sred[w];
        float s_fsum  = sr[0],  s_shsum = sr[16], s_dmsq = sr[8],  s_uss = sr[24];
        float s_cossum= sr[4],  s_cossq = sr[20], s_dirch= sr[12];
        float s_csum  = sr[28], s_cssum = sr[2],  s_tdp  = sr[18];
        float nsq = sr[10]*sr[10] + sr[26]*sr[26] + sr[6]*sr[6] + sr[22]*sr[22]
                  + sr[14]*sr[14] + sr[30]*sr[30] + sr[1]*sr[1] + sr[17]*sr[17]
                  + sr[9]*sr[9]   + sr[25]*sr[25];
        float s_maxdm = sr[32], s_maxcs = sr[48], s_mincs = -sr[40];

        float path = s_fsum + s_shsum - dhalf;
        float total_disp = (s_tdp > 0.f) ? sqrtf(fmaxf(s_tdp, 1e-30f)) : 0.f;
        float disp_ratio = __fdividef(total_disp, path + F_EPS);
        float loop_score = 1.f - disp_ratio;
        float ncf  = (float)(n - 2);
        float rncf = __fdividef(1.f, ncf);
        float mean_cos  = s_cossum * rncf;
        float mean_curv = 1.f - mean_cos;
        float max_curv  = 1.0f - s_mincs;
        float cvsq      = ncf - 2.0f * s_cossum + s_cossq;
        float curv_var  = (cvsq - ncf * mean_curv * mean_curv)
                          * __fdividef(1.f, fmaxf(ncf - 1.f, 1.f));
        float std_curv  = (ncf > 1.f) ? sqrtf(fmaxf(curv_var, 1e-30f)) : 0.f;
        float curv_range = s_maxcs - s_mincs;
        float dir_chg   = s_dirch * rncf;
        float fh = s_fsum  * __fdividef(1.f, (float)(half + 1));
        float sh = s_shsum * __fdividef(1.f, (float)(m - half));
        float conv = __fdividef(fh - sh, fh + F_EPS);
        float casc = -conv;
        float npairs = mf * (mf - 1.f) * 0.5f;
        float par = 0.5f * (nsq - s_uss) * __fdividef(1.f, fmaxf(npairs, 1.f));
        float rmf = __fdividef(1.f, mf);
        float mean_dm = path * rmf;
        float dm_var  = (s_dmsq - mf * mean_dm * mean_dm)
                        * __fdividef(1.f, fmaxf(mf - 1.f, 1.f));
        float std_dm  = sqrtf(fmaxf(dm_var, 1e-30f));
        float jump = (mean_dm > F_EPS) ? __fdividef(s_maxdm, mean_dm) : 1.f;
        float cnt  = nf * (float)MD;
        float mc   = s_csum * __fdividef(1.f, cnt);
        float cvar = (s_cssum - cnt * mc * mc) * __fdividef(1.f, cnt - 1.f);
        float stdc = sqrtf(fmaxf(cvar, 1e-30f));

        float* sf = sfeat[w];
        sf[0]  = total_disp;  sf[1]  = path;        sf[2]  = disp_ratio;
        sf[3]  = nf * 0.1f;   sf[4]  = mean_curv;   sf[5]  = max_curv;
        sf[6]  = std_curv;    sf[7]  = curv_range;  sf[8]  = mean_cos;
        sf[9]  = s_mincs;     sf[10] = dir_chg;     sf[11] = disp_ratio;
        sf[12] = loop_score;  sf[13] = conv;        sf[14] = par;
        sf[15] = jump;        sf[16] = casc;        sf[17] = mean_dm;
        sf[18] = std_dm;      sf[19] = mc;          sf[20] = stdc;
    }
    __syncwarp();

    if (lane < 15) {
        float4 v = *(const float4*)&sfeat[w][lane * 4];
        *(float4*)(g_feats + (size_t)traj * 64 + lane * 4) = v;
    }
}

// --------------------- K2: GEMM + LayerNorm + GELU --------------------------
__device__ __forceinline__ unsigned long long pk2(float a, float b) {
    unsigned long long r;
    asm("mov.b64 %0, {%1, %2};" : "=l"(r) : "f"(a), "f"(b));
    return r;
}
__device__ __forceinline__ void upk2(unsigned long long v, float& a, float& b) {
    asm("mov.b64 {%0, %1}, %2;" : "=f"(a), "=f"(b) : "l"(v));
}
__device__ __forceinline__ unsigned long long fma2(unsigned long long a,
                                                   unsigned long long b,
                                                   unsigned long long c) {
    unsigned long long d;
    asm("fma.rn.f32x2 %0, %1, %2, %3;" : "=l"(d) : "l"(a), "l"(b), "l"(c));
    return d;
}

__global__ void __launch_bounds__(128)
k2_head(const float* __restrict__ Wg, const float* __restrict__ bg,
        const float* __restrict__ lnwg, const float* __restrict__ lnbg,
        float* __restrict__ out, int B)
{
    // transposed feats: sfe_t[f * 64 + row]  (15.36 KB)
    __shared__ alignas(16) float sfe_t[NF * TB];

    const int tid = threadIdx.x;
    const int t0  = blockIdx.x * TB;

    // stage + transpose: lane handles (row=i&63, q=i>>6); stores conflict-free
    for (int i = tid; i < TB * 15; i += 128) {
        int r = i & 63;
        int q = i >> 6;
        float4 v = __ldg((const float4*)(g_feats + (size_t)(t0 + r) * 64) + q);
        int f4 = q * 4;
        sfe_t[(f4 + 0) * TB + r] = v.x;
        sfe_t[(f4 + 1) * TB + r] = v.y;
        sfe_t[(f4 + 2) * TB + r] = v.z;
        sfe_t[(f4 + 3) * TB + r] = v.w;
    }
    __syncthreads();

    const int tx = tid & 7;               // 8 column groups of 6
    const int ty = tid >> 3;              // 16 row groups of 4
    const int colb = tx * 6;

    unsigned long long acc[4][3];
    {
        float2 bb0 = __ldg((const float2*)(bg + colb));
        float2 bb1 = __ldg((const float2*)(bg + colb + 2));
        float2 bb2 = __ldg((const float2*)(bg + colb + 4));
        unsigned long long b0 = pk2(bb0.x, bb0.y);
        unsigned long long b1 = pk2(bb1.x, bb1.y);
        unsigned long long b2 = pk2(bb2.x, bb2.y);
#pragma unroll
        for (int r = 0; r < 4; r++) { acc[r][0] = b0; acc[r][1] = b1; acc[r][2] = b2; }
    }

    const float* fvbase = sfe_t + ty * 4;   // + f*64 per iteration
#pragma unroll 6
    for (int f = 0; f < NF; f++) {
        // W row f, this thread's 6 cols (L1-resident across blocks)
        float2 wa = __ldg((const float2*)(Wg + f * H + colb));
        float2 wb = __ldg((const float2*)(Wg + f * H + colb + 2));
        float2 wc = __ldg((const float2*)(Wg + f * H + colb + 4));
        unsigned long long w0 = pk2(wa.x, wa.y);
        unsigned long long w1 = pk2(wb.x, wb.y);
        unsigned long long w2 = pk2(wc.x, wc.y);
        // one LDS.128 = fv for all 4 rows (conflict-free)
        float4 fvv = *(const float4*)(fvbase + f * TB);
        unsigned long long fp0 = pk2(fvv.x, fvv.x);
        unsigned long long fp1 = pk2(fvv.y, fvv.y);
        unsigned long long fp2 = pk2(fvv.z, fvv.z);
        unsigned long long fp3 = pk2(fvv.w, fvv.w);
        acc[0][0] = fma2(fp0, w0, acc[0][0]);
        acc[0][1] = fma2(fp0, w1, acc[0][1]);
        acc[0][2] = fma2(fp0, w2, acc[0][2]);
        acc[1][0] = fma2(fp1, w0, acc[1][0]);
        acc[1][1] = fma2(fp1, w1, acc[1][1]);
        acc[1][2] = fma2(fp1, w2, acc[1][2]);
        acc[2][0] = fma2(fp2, w0, acc[2][0]);
        acc[2][1] = fma2(fp2, w1, acc[2][1]);
        acc[2][2] = fma2(fp2, w2, acc[2][2]);
        acc[3][0] = fma2(fp3, w0, acc[3][0]);
        acc[3][1] = fma2(fp3, w1, acc[3][1]);
        acc[3][2] = fma2(fp3, w2, acc[3][2]);
    }

    float lw[6], lb[6];
    {
        float2 a0 = __ldg((const float2*)(lnwg + colb));
        float2 a1 = __ldg((const float2*)(lnwg + colb + 2));
        float2 a2 = __ldg((const float2*)(lnwg + colb + 4));
        lw[0]=a0.x; lw[1]=a0.y; lw[2]=a1.x; lw[3]=a1.y; lw[4]=a2.x; lw[5]=a2.y;
        float2 c0 = __ldg((const float2*)(lnbg + colb));
        float2 c1 = __ldg((const float2*)(lnbg + colb + 2));
        float2 c2 = __ldg((const float2*)(lnbg + colb + 4));
        lb[0]=c0.x; lb[1]=c0.y; lb[2]=c1.x; lb[3]=c1.y; lb[4]=c2.x; lb[5]=c2.y;
    }

#pragma unroll
    for (int r = 0; r < 4; r++) {
        float x[6];
        upk2(acc[r][0], x[0], x[1]);
        upk2(acc[r][1], x[2], x[3]);
        upk2(acc[r][2], x[4], x[5]);
        float s = 0.f, sq = 0.f;
#pragma unroll
        for (int c = 0; c < 6; c++) { s += x[c]; sq += x[c] * x[c]; }
#pragma unroll
        for (int o = 1; o < 8; o <<= 1) {
            s  += __shfl_xor_sync(FULLM, s,  o);
            sq += __shfl_xor_sync(FULLM, sq, o);
        }
        float mu  = s * (1.0f / 48.0f);
        float var = sq * (1.0f / 48.0f) - mu * mu;
        float inv = rsqrtf(var + 1e-5f);

        int row = t0 + ty * 4 + r;
        if (row < B) {
            float y[6];
#pragma unroll
            for (int c = 0; c < 6; c++) {
                float v = (x[c] - mu) * inv * lw[c] + lb[c];
                y[c] = v * normcdff(v);          // exact GELU: x * Phi(x)
            }
            float* op = out + (size_t)row * H + colb;
            *(float2*)(op + 0) = make_float2(y[0], y[1]);
            *(float2*)(op + 2) = make_float2(y[2], y[3]);
            *(float2*)(op + 4) = make_float2(y[4], y[5]);
        }
    }
}

extern "C" void kernel_launch(void* const* d_in, const int* in_sizes, int n_in,
                              void* d_out, int out_size) {
    const float* coords  = (const float*)d_in[0];
    const int*   lengths = (const int*)d_in[1];
    const float* W       = (const float*)d_in[2];
    const float* b       = (const float*)d_in[3];
    const float* lnw     = (const float*)d_in[4];
    const float* lnb     = (const float*)d_in[5];
    float* out = (float*)d_out;

    int B = in_sizes[1];
    int g1 = (B + WPB - 1) / WPB;
    k1_features<<<g1, TPB1>>>(coords, lengths, B);
    int g2 = (B + TB - 1) / TB;
    k2_head<<<g2, 128>>>(W, b, lnw, lnb, out, B);
}